// round 7
// baseline (speedup 1.0000x reference)
#include <cuda_runtime.h>
#include <cuda_bf16.h>
#include <math.h>
#include <stdint.h>

#define S_LEN 2048
#define HID   3584
#define NH    28
#define NKV   4
#define HD    128
#define KV_DIM 512
#define QKV_N  4608   // 3584 + 512 + 512

// ---------------- scratch (__device__ globals; no allocs allowed) ----------
__device__ float g_Q[S_LEN * HID];
__device__ float g_K[S_LEN * KV_DIM];
__device__ float g_V[S_LEN * KV_DIM];
__device__ float g_A[S_LEN * HID];

__device__ __nv_bfloat16 g_Xhi[S_LEN * HID];
__device__ __nv_bfloat16 g_Xlo[S_LEN * HID];
__device__ __nv_bfloat16 g_Ahi[S_LEN * HID];
__device__ __nv_bfloat16 g_Alo[S_LEN * HID];
__device__ __nv_bfloat16 g_Wt_hi[(size_t)QKV_N * HID];
__device__ __nv_bfloat16 g_Wt_lo[(size_t)QKV_N * HID];
__device__ __nv_bfloat16 g_Wo_hi[(size_t)HID * HID];
__device__ __nv_bfloat16 g_Wo_lo[(size_t)HID * HID];

__device__ __nv_bfloat16 g_Qh[S_LEN * HID];
__device__ __nv_bfloat16 g_Ql[S_LEN * HID];
__device__ __nv_bfloat16 g_Kh[S_LEN * KV_DIM];
__device__ __nv_bfloat16 g_Kl[S_LEN * KV_DIM];
__device__ __nv_bfloat16 g_Vh[S_LEN * KV_DIM];
__device__ __nv_bfloat16 g_Vl[S_LEN * KV_DIM];

// ---------------- PTX helpers (baseline PTX only) ---------------------------
__device__ __forceinline__ uint32_t smem_u32(const void* p) {
    uint32_t a;
    asm("{ .reg .u64 t; cvta.to.shared.u64 t, %1; cvt.u32.u64 %0, t; }" : "=r"(a) : "l"(p));
    return a;
}
__device__ __forceinline__ void cp_async16(uint32_t dst, const void* src) {
    asm volatile("cp.async.cg.shared.global [%0], [%1], 16;" :: "r"(dst), "l"(src));
}
#define CP_COMMIT() asm volatile("cp.async.commit_group;" ::: "memory")
#define CP_WAIT(N)  asm volatile("cp.async.wait_group %0;" :: "n"(N) : "memory")

__device__ __forceinline__ void ldm4(uint32_t* r, uint32_t addr) {
    asm volatile("ldmatrix.sync.aligned.m8n8.x4.shared.b16 {%0,%1,%2,%3}, [%4];"
        : "=r"(r[0]), "=r"(r[1]), "=r"(r[2]), "=r"(r[3]) : "r"(addr));
}
__device__ __forceinline__ void ldm4t(uint32_t* r, uint32_t addr) {
    asm volatile("ldmatrix.sync.aligned.m8n8.x4.trans.shared.b16 {%0,%1,%2,%3}, [%4];"
        : "=r"(r[0]), "=r"(r[1]), "=r"(r[2]), "=r"(r[3]) : "r"(addr));
}
__device__ __forceinline__ void mma16816(float* c, const uint32_t* a, const uint32_t* b) {
    asm volatile("mma.sync.aligned.m16n8k16.row.col.f32.bf16.bf16.f32 "
        "{%0,%1,%2,%3}, {%4,%5,%6,%7}, {%8,%9}, {%0,%1,%2,%3};"
        : "+f"(c[0]), "+f"(c[1]), "+f"(c[2]), "+f"(c[3])
        : "r"(a[0]), "r"(a[1]), "r"(a[2]), "r"(a[3]), "r"(b[0]), "r"(b[1]));
}
__device__ __forceinline__ uint32_t packbf2(float lo, float hi) {
    __nv_bfloat162 t = __floats2bfloat162_rn(lo, hi);
    return *(uint32_t*)&t;
}

// ---------------- pre-processing kernels ------------------------------------
__global__ void split_x_kernel(const float* __restrict__ X) {
    int i = blockIdx.x * blockDim.x + threadIdx.x;
    if (i < S_LEN * HID) {
        float x = X[i];
        __nv_bfloat16 h = __float2bfloat16(x);
        g_Xhi[i] = h;
        g_Xlo[i] = __float2bfloat16(x - __bfloat162float(h));
    }
}
__global__ void split_a_kernel() {
    int i = blockIdx.x * blockDim.x + threadIdx.x;
    if (i < S_LEN * HID) {
        float x = g_A[i];
        __nv_bfloat16 h = __float2bfloat16(x);
        g_Ahi[i] = h;
        g_Alo[i] = __float2bfloat16(x - __bfloat162float(h));
    }
}
__global__ void qkv_split_kernel() {
    int i = blockIdx.x * blockDim.x + threadIdx.x;
    const int NQ = S_LEN * HID, NKVE = S_LEN * KV_DIM;
    if (i < NQ) {
        float x = g_Q[i];
        __nv_bfloat16 h = __float2bfloat16(x);
        g_Qh[i] = h;
        g_Ql[i] = __float2bfloat16(x - __bfloat162float(h));
    } else if (i < NQ + NKVE) {
        int j = i - NQ;
        float x = g_K[j];
        __nv_bfloat16 h = __float2bfloat16(x);
        g_Kh[j] = h;
        g_Kl[j] = __float2bfloat16(x - __bfloat162float(h));
    } else if (i < NQ + 2 * NKVE) {
        int j = i - NQ - NKVE;
        float x = g_V[j];
        __nv_bfloat16 h = __float2bfloat16(x);
        g_Vh[j] = h;
        g_Vl[j] = __float2bfloat16(x - __bfloat162float(h));
    }
}

__global__ void transpose_split(const float* __restrict__ W, int K, int N,
                                int dstSel, size_t dstOff) {
    __nv_bfloat16* Th = (dstSel ? g_Wo_hi : g_Wt_hi) + dstOff;
    __nv_bfloat16* Tl = (dstSel ? g_Wo_lo : g_Wt_lo) + dstOff;
    __shared__ float t[32][33];
    int n0 = blockIdx.x * 32, k0 = blockIdx.y * 32;
    int tx = threadIdx.x, ty = threadIdx.y;
#pragma unroll
    for (int i = 0; i < 32; i += 8)
        t[ty + i][tx] = W[(size_t)(k0 + ty + i) * N + n0 + tx];
    __syncthreads();
#pragma unroll
    for (int i = 0; i < 32; i += 8) {
        int n = n0 + ty + i, k = k0 + tx;
        float x = t[tx][ty + i];
        __nv_bfloat16 h = __float2bfloat16(x);
        Th[(size_t)n * K + k] = h;
        Tl[(size_t)n * K + k] = __float2bfloat16(x - __bfloat162float(h));
    }
}

// ---------------- HMMA bf16x3 GEMM: CTA 128x256, warp 64x64, 3-stage --------
// row stride 40 bf16 = 80 B (ldmatrix conflict-free: banks 20r mod 32 distinct)
#define ROWB 80
#define SA_HI 0
#define SA_LO 10240
#define SB_HI 20480
#define SB_LO 40960
#define STG_B 61440                 // bytes per stage
#define GEMM_SMEM (3 * STG_B)       // 184320

__device__ __forceinline__ void gemm_tile(
    const __nv_bfloat16* __restrict__ Ah, const __nv_bfloat16* __restrict__ Al,
    const __nv_bfloat16* __restrict__ Bh, const __nv_bfloat16* __restrict__ Bl,
    int Kd, int bm, int bnB, float* __restrict__ C, int ldc, int bnC)
{
    extern __shared__ char smem[];
    const uint32_t sbase = smem_u32(smem);
    const int tid  = threadIdx.x;
    const int wid  = tid >> 5;
    const int lane = tid & 31;
    const int nch  = Kd >> 5;

    const int mw = (wid >> 2) * 64;      // warp M offset (0 / 64)
    const int nw = (wid & 3) * 64;       // warp N offset (0/64/128/192)

    const int rowAb = mw + (lane & 15);
    const int colA  = (lane >> 4) << 3;
    const int rowBb = nw + (lane & 7) + ((lane >> 4) << 3);
    const int colB  = ((lane >> 3) & 1) << 3;

    float acc[4][8][4];
#pragma unroll
    for (int mt = 0; mt < 4; ++mt)
#pragma unroll
        for (int nb = 0; nb < 8; ++nb)
#pragma unroll
            for (int q = 0; q < 4; ++q) acc[mt][nb][q] = 0.f;

    // stage loader: 3072 x 16B segments, 12 per thread
    auto load_stage = [&](int ci, int slot) {
        const int k0 = ci << 5;
        const uint32_t st = sbase + slot * STG_B;
#pragma unroll
        for (int it = 0; it < 12; ++it) {
            int u = tid + it * 256;
            const __nv_bfloat16* src;
            uint32_t dst;
            if (u < 1024) {                 // A: hi | lo
                int v = u & 511, row = v >> 2, seg = v & 3;
                src = (u < 512 ? Ah : Al) + (size_t)(bm + row) * Kd + k0 + seg * 8;
                dst = st + (u < 512 ? SA_HI : SA_LO) + row * ROWB + seg * 16;
            } else {                        // B: hi | lo
                int u2 = u - 1024;
                int v = u2 & 1023, row = v >> 2, seg = v & 3;
                src = (u2 < 1024 ? Bh : Bl) + (size_t)(bnB + row) * Kd + k0 + seg * 8;
                dst = st + (u2 < 1024 ? SB_HI : SB_LO) + row * ROWB + seg * 16;
            }
            cp_async16(dst, src);
        }
        CP_COMMIT();
    };

    load_stage(0, 0);
    load_stage(1, 1);

    for (int i = 0; i < nch; ++i) {
        CP_WAIT(1);                 // stage i resident
        __syncthreads();            // all warps done with stage i-1 (slot reuse safe)
        if (i + 2 < nch) load_stage(i + 2, (i + 2) % 3);

        const uint32_t sb = sbase + (i % 3) * STG_B;
#pragma unroll
        for (int kk = 0; kk < 32; kk += 16) {
            uint32_t fAh[4][4], fAl[4][4];
#pragma unroll
            for (int mt = 0; mt < 4; ++mt) {
                uint32_t ra = sb + (rowAb + mt * 16) * ROWB + (kk + colA) * 2;
                ldm4(fAh[mt], ra + SA_HI);
                ldm4(fAl[mt], ra + SA_LO);
            }
#pragma unroll
            for (int np = 0; np < 4; ++np) {
                uint32_t fBh[4], fBl[4];
                uint32_t rb = sb + SB_HI + (rowBb + np * 16) * ROWB + (kk + colB) * 2;
                ldm4(fBh, rb);
                ldm4(fBl, rb + (SB_LO - SB_HI));
#pragma unroll
                for (int half = 0; half < 2; ++half) {
                    int nb = np * 2 + half;
#pragma unroll
                    for (int mt = 0; mt < 4; ++mt) {
                        mma16816(acc[mt][nb], fAh[mt], &fBh[half * 2]);
                        mma16816(acc[mt][nb], fAh[mt], &fBl[half * 2]);
                        mma16816(acc[mt][nb], fAl[mt], &fBh[half * 2]);
                    }
                }
            }
        }
    }

    // epilogue: direct fp32 stores
#pragma unroll
    for (int mt = 0; mt < 4; ++mt)
#pragma unroll
        for (int nb = 0; nb < 8; ++nb) {
            int r0 = bm + mw + mt * 16 + (lane >> 2);
            int c0 = bnC + nw + nb * 8 + (lane & 3) * 2;
            float2 v0 = {acc[mt][nb][0], acc[mt][nb][1]};
            float2 v1 = {acc[mt][nb][2], acc[mt][nb][3]};
            *(float2*)(C + (size_t)r0 * ldc + c0)       = v0;
            *(float2*)(C + (size_t)(r0 + 8) * ldc + c0) = v1;
        }
}

__global__ __launch_bounds__(256, 1) void qkv_gemm_kernel() {
    int bn = blockIdx.x * 256;
    int bm = blockIdx.y * 128;
    float* C; int ldc, cn;
    if (bn < HID)            { C = g_Q; ldc = HID;    cn = bn; }
    else if (bn < HID + 512) { C = g_K; ldc = KV_DIM; cn = bn - HID; }
    else                     { C = g_V; ldc = KV_DIM; cn = bn - HID - 512; }
    gemm_tile(g_Xhi, g_Xlo, g_Wt_hi, g_Wt_lo, HID, bm, bn, C, ldc, cn);
}

__global__ __launch_bounds__(256, 1) void out_gemm_kernel(float* __restrict__ out) {
    gemm_tile(g_Ahi, g_Alo, g_Wo_hi, g_Wo_lo, HID,
              blockIdx.y * 128, blockIdx.x * 256, out, HID, blockIdx.x * 256);
}

// ---------------- RoPE ------------------------------------------------------
__global__ void rope_kernel(const int* __restrict__ pos_ids)
{
    int idx = blockIdx.x * blockDim.x + threadIdx.x;
    if (idx >= S_LEN * (NH + NKV) * 64) return;
    int i  = idx & 63;
    int t  = idx >> 6;
    int hh = t & 31;
    int s  = t >> 5;

    float inv_freq = expf(-(float)i * 0.21586735246819178f);
    float ang = (float)pos_ids[s] * inv_freq;
    float sv, cv;
    sincosf(ang, &sv, &cv);

    float* p;
    if (hh < NH) p = g_Q + (size_t)s * HID    + hh * 128;
    else         p = g_K + (size_t)s * KV_DIM + (hh - NH) * 128;
    float x0 = p[i], x1 = p[i + 64];
    p[i]      = x0 * cv - x1 * sv;
    p[i + 64] = x1 * cv + x0 * sv;
}

// ---------------- HMMA bf16x3 flash attention (unchanged from R4) ------------
#define FS 136
#define F_QH 0
#define F_QL (64 * FS)
#define F_KH (2 * 64 * FS)
#define F_KL (3 * 64 * FS)
#define F_VH (4 * 64 * FS)
#define F_VL (5 * 64 * FS)
#define FLASH_SMEM (6 * 64 * FS * 2)

__global__ __launch_bounds__(128) void flash_kernel()
{
    const int qt  = (int)gridDim.x - 1 - (int)blockIdx.x;
    const int h   = blockIdx.y;
    const int kvh = h / (NH / NKV);

    extern __shared__ __nv_bfloat16 fsm[];
    const uint32_t sb = smem_u32(fsm);

    const int tid  = threadIdx.x;
    const int w    = tid >> 5;
    const int lane = tid & 31;

    const int rowA   = w * 16 + (lane & 15);
    const int colA   = (lane >> 4) << 3;
    const int rowBo  = (lane & 7) + ((lane >> 4) << 3);
    const int colB   = ((lane >> 3) & 1) << 3;
    const int rowVt  = (lane & 7) + (((lane >> 3) & 1) << 3);
    const int colVt  = (lane >> 4) << 3;

    for (int f = tid; f < 1024; f += 128) {
        int r = f >> 4, seg = f & 15;
        size_t g = (size_t)(qt * 64 + r) * HID + h * 128 + seg * 8;
        *(uint4*)&fsm[F_QH + r * FS + seg * 8] = *(const uint4*)&g_Qh[g];
        *(uint4*)&fsm[F_QL + r * FS + seg * 8] = *(const uint4*)&g_Ql[g];
    }

    float o[16][4];
#pragma unroll
    for (int nb = 0; nb < 16; ++nb)
#pragma unroll
        for (int q = 0; q < 4; ++q) o[nb][q] = 0.f;
    float m0 = -1e30f, m1 = -1e30f, l0 = 0.f, l1 = 0.f;

    const float SL = 0.08838834764831845f * 1.4426950408889634f;

    for (int kt = 0; kt <= qt; ++kt) {
        __syncthreads();
        for (int f = tid; f < 1024; f += 128) {
            int r = f >> 4, seg = f & 15;
            size_t g = (size_t)(kt * 64 + r) * KV_DIM + kvh * 128 + seg * 8;
            *(uint4*)&fsm[F_KH + r * FS + seg * 8] = *(const uint4*)&g_Kh[g];
            *(uint4*)&fsm[F_KL + r * FS + seg * 8] = *(const uint4*)&g_Kl[g];
            *(uint4*)&fsm[F_VH + r * FS + seg * 8] = *(const uint4*)&g_Vh[g];
            *(uint4*)&fsm[F_VL + r * FS + seg * 8] = *(const uint4*)&g_Vl[g];
        }
        __syncthreads();

        float s[8][4];
#pragma unroll
        for (int nb = 0; nb < 8; ++nb)
#pragma unroll
            for (int q = 0; q < 4; ++q) s[nb][q] = 0.f;

#pragma unroll
        for (int ks = 0; ks < 8; ++ks) {
            uint32_t qh[4], ql[4];
            uint32_t ra = sb + (rowA * FS + ks * 16 + colA) * 2;
            ldm4(qh, ra + F_QH * 2);
            ldm4(ql, ra + F_QL * 2);
#pragma unroll
            for (int np = 0; np < 4; ++np) {
                uint32_t kh[4], kl[4];
                uint32_t rb = sb + ((np * 16 + rowBo) * FS + ks * 16 + colB) * 2;
                ldm4(kh, rb + F_KH * 2);
                ldm4(kl, rb + F_KL * 2);
#pragma unroll
                for (int half = 0; half < 2; ++half) {
                    int nb = np * 2 + half;
                    mma16816(s[nb], qh, &kh[half * 2]);
                    mma16816(s[nb], qh, &kl[half * 2]);
                    mma16816(s[nb], ql, &kh[half * 2]);
                }
            }
        }

        const bool diag = (kt == qt);
        const int rl0 = w * 16 + (lane >> 2);
        const int rl1 = rl0 + 8;
        float mx0 = -1e30f, mx1 = -1e30f;
#pragma unroll
        for (int nb = 0; nb < 8; ++nb) {
            int c0 = nb * 8 + (lane & 3) * 2;
#pragma unroll
            for (int q = 0; q < 4; ++q) {
                float v = s[nb][q] * SL;
                if (diag) {
                    int col = c0 + (q & 1);
                    int row = (q < 2) ? rl0 : rl1;
                    if (col > row) v = -1e30f;
                }
                s[nb][q] = v;
            }
            mx0 = fmaxf(mx0, fmaxf(s[nb][0], s[nb][1]));
            mx1 = fmaxf(mx1, fmaxf(s[nb][2], s[nb][3]));
        }
        mx0 = fmaxf(mx0, __shfl_xor_sync(0xffffffffu, mx0, 1));
        mx0 = fmaxf(mx0, __shfl_xor_sync(0xffffffffu, mx0, 2));
        mx1 = fmaxf(mx1, __shfl_xor_sync(0xffffffffu, mx1, 1));
        mx1 = fmaxf(mx1, __shfl_xor_sync(0xffffffffu, mx1, 2));

        float mn0 = fmaxf(m0, mx0), mn1 = fmaxf(m1, mx1);
        float a0 = exp2f(m0 - mn0), a1 = exp2f(m1 - mn1);
        float ls0 = 0.f, ls1 = 0.f;
#pragma unroll
        for (int nb = 0; nb < 8; ++nb) {
            float p0 = exp2f(s[nb][0] - mn0);
            float p1 = exp2f(s[nb][1] - mn0);
            float p2 = exp2f(s[nb][2] - mn1);
            float p3 = exp2f(s[nb][3] - mn1);
            s[nb][0] = p0; s[nb][1] = p1; s[nb][2] = p2; s[nb][3] = p3;
            ls0 += p0 + p1;
            ls1 += p2 + p3;
        }
        ls0 += __shfl_xor_sync(0xffffffffu, ls0, 1);
        ls0 += __shfl_xor_sync(0xffffffffu, ls0, 2);
        ls1 += __shfl_xor_sync(0xffffffffu, ls1, 1);
        ls1 += __shfl_xor_sync(0xffffffffu, ls1, 2);
        l0 = l0 * a0 + ls0;
        l1 = l1 * a1 + ls1;
        m0 = mn0; m1 = mn1;

#pragma unroll
        for (int nb = 0; nb < 16; ++nb) {
            o[nb][0] *= a0; o[nb][1] *= a0;
            o[nb][2] *= a1; o[nb][3] *= a1;
        }

        uint32_t pah[4][4], pal[4][4];
#pragma unroll
        for (int kb = 0; kb < 4; ++kb) {
#pragma unroll
            for (int part = 0; part < 4; ++part) {
                int nb = 2 * kb + (part >> 1);
                float c0 = s[nb][(part & 1) * 2];
                float c1 = s[nb][(part & 1) * 2 + 1];
                __nv_bfloat162 hi2 = __floats2bfloat162_rn(c0, c1);
                pah[kb][part] = *(uint32_t*)&hi2;
                float r0 = c0 - __bfloat162float(hi2.x);
                float r1 = c1 - __bfloat162float(hi2.y);
                pal[kb][part] = packbf2(r0, r1);
            }
        }

#pragma unroll
        for (int kb = 0; kb < 4; ++kb) {
#pragma unroll
            for (int nv = 0; nv < 8; ++nv) {
                uint32_t vh[4], vl[4];
                uint32_t rv = sb + ((kb * 16 + rowVt) * FS + nv * 16 + colVt) * 2;
                ldm4t(vh, rv + F_VH * 2);
                ldm4t(vl, rv + F_VL * 2);
#pragma unroll
                for (int half = 0; half < 2; ++half) {
                    int nbv = nv * 2 + half;
                    mma16816(o[nbv], pah[kb], &vh[half * 2]);
                    mma16816(o[nbv], pal[kb], &vh[half * 2]);
                    mma16816(o[nbv], pah[kb], &vl[half * 2]);
                }
            }
        }
    }

    const float inv0 = 1.0f / l0, inv1 = 1.0f / l1;
    const int r0 = qt * 64 + w * 16 + (lane >> 2);
    const int r1 = r0 + 8;
#pragma unroll
    for (int nb = 0; nb < 16; ++nb) {
        int c = h * 128 + nb * 8 + (lane & 3) * 2;
        float2 v0 = {o[nb][0] * inv0, o[nb][1] * inv0};
        float2 v1 = {o[nb][2] * inv1, o[nb][3] * inv1};
        *(float2*)&g_A[(size_t)r0 * HID + c] = v0;
        *(float2*)&g_A[(size_t)r1 * HID + c] = v1;
    }
}

// ---------------------------------------------------------------------------
extern "C" void kernel_launch(void* const* d_in, const int* in_sizes, int n_in,
                              void* d_out, int out_size)
{
    const float* X   = (const float*)d_in[0];
    const int*   pid = (const int*)  d_in[1];
    const float* Wq  = (const float*)d_in[2];
    const float* Wk  = (const float*)d_in[3];
    const float* Wv  = (const float*)d_in[4];
    const float* Wo  = (const float*)d_in[5];
    float* out = (float*)d_out;

    static int attr_set = 0;
    if (!attr_set) {
        cudaFuncSetAttribute(qkv_gemm_kernel, cudaFuncAttributeMaxDynamicSharedMemorySize, GEMM_SMEM);
        cudaFuncSetAttribute(out_gemm_kernel, cudaFuncAttributeMaxDynamicSharedMemorySize, GEMM_SMEM);
        cudaFuncSetAttribute(flash_kernel, cudaFuncAttributeMaxDynamicSharedMemorySize, FLASH_SMEM);
        attr_set = 1;
    }

    split_x_kernel<<<(S_LEN * HID + 255) / 256, 256>>>(X);

    transpose_split<<<dim3(HID / 32, HID / 32), dim3(32, 8)>>>(Wq, HID, HID, 0, 0);
    transpose_split<<<dim3(KV_DIM / 32, HID / 32), dim3(32, 8)>>>(
        Wk, HID, KV_DIM, 0, (size_t)HID * HID);
    transpose_split<<<dim3(KV_DIM / 32, HID / 32), dim3(32, 8)>>>(
        Wv, HID, KV_DIM, 0, (size_t)(HID + 512) * HID);
    transpose_split<<<dim3(HID / 32, HID / 32), dim3(32, 8)>>>(Wo, HID, HID, 1, 0);

    qkv_gemm_kernel<<<dim3(QKV_N / 256, S_LEN / 128), 256, GEMM_SMEM>>>();

    rope_kernel<<<(S_LEN * 32 * 64 + 255) / 256, 256>>>(pid);

    int nsplit = S_LEN * HID + 2 * S_LEN * KV_DIM;
    qkv_split_kernel<<<(nsplit + 255) / 256, 256>>>();

    flash_kernel<<<dim3(32, 28), 128, FLASH_SMEM>>>();

    split_a_kernel<<<(S_LEN * HID + 255) / 256, 256>>>();

    out_gemm_kernel<<<dim3(HID / 256, S_LEN / 128), 256, GEMM_SMEM>>>(out);
}

// round 8
// speedup vs baseline: 1.0150x; 1.0150x over previous
#include <cuda_runtime.h>
#include <cuda_bf16.h>
#include <math.h>
#include <stdint.h>

#define S_LEN 2048
#define HID   3584
#define NH    28
#define NKV   4
#define HD    128
#define KV_DIM 512
#define QKV_N  4608   // 3584 + 512 + 512

// ---------------- scratch (__device__ globals; no allocs allowed) ----------
__device__ __nv_bfloat16 g_Xhi[S_LEN * HID];
__device__ __nv_bfloat16 g_Xlo[S_LEN * HID];
__device__ __nv_bfloat16 g_Ahi[S_LEN * HID];
__device__ __nv_bfloat16 g_Alo[S_LEN * HID];
__device__ __nv_bfloat16 g_Wt_hi[(size_t)QKV_N * HID];
__device__ __nv_bfloat16 g_Wt_lo[(size_t)QKV_N * HID];
__device__ __nv_bfloat16 g_Wo_hi[(size_t)HID * HID];
__device__ __nv_bfloat16 g_Wo_lo[(size_t)HID * HID];

__device__ __nv_bfloat16 g_Qh[S_LEN * HID];
__device__ __nv_bfloat16 g_Ql[S_LEN * HID];
__device__ __nv_bfloat16 g_Kh[S_LEN * KV_DIM];
__device__ __nv_bfloat16 g_Kl[S_LEN * KV_DIM];
__device__ __nv_bfloat16 g_Vh[S_LEN * KV_DIM];
__device__ __nv_bfloat16 g_Vl[S_LEN * KV_DIM];

// ---------------- PTX helpers (baseline PTX only) ---------------------------
__device__ __forceinline__ uint32_t smem_u32(const void* p) {
    uint32_t a;
    asm("{ .reg .u64 t; cvta.to.shared.u64 t, %1; cvt.u32.u64 %0, t; }" : "=r"(a) : "l"(p));
    return a;
}
__device__ __forceinline__ void cp_async16(uint32_t dst, const void* src) {
    asm volatile("cp.async.cg.shared.global [%0], [%1], 16;" :: "r"(dst), "l"(src));
}
#define CP_COMMIT() asm volatile("cp.async.commit_group;" ::: "memory")
#define CP_WAIT(N)  asm volatile("cp.async.wait_group %0;" :: "n"(N) : "memory")

__device__ __forceinline__ void ldm4(uint32_t* r, uint32_t addr) {
    asm volatile("ldmatrix.sync.aligned.m8n8.x4.shared.b16 {%0,%1,%2,%3}, [%4];"
        : "=r"(r[0]), "=r"(r[1]), "=r"(r[2]), "=r"(r[3]) : "r"(addr));
}
__device__ __forceinline__ void ldm4t(uint32_t* r, uint32_t addr) {
    asm volatile("ldmatrix.sync.aligned.m8n8.x4.trans.shared.b16 {%0,%1,%2,%3}, [%4];"
        : "=r"(r[0]), "=r"(r[1]), "=r"(r[2]), "=r"(r[3]) : "r"(addr));
}
__device__ __forceinline__ void mma16816(float* c, const uint32_t* a, const uint32_t* b) {
    asm volatile("mma.sync.aligned.m16n8k16.row.col.f32.bf16.bf16.f32 "
        "{%0,%1,%2,%3}, {%4,%5,%6,%7}, {%8,%9}, {%0,%1,%2,%3};"
        : "+f"(c[0]), "+f"(c[1]), "+f"(c[2]), "+f"(c[3])
        : "r"(a[0]), "r"(a[1]), "r"(a[2]), "r"(a[3]), "r"(b[0]), "r"(b[1]));
}
__device__ __forceinline__ uint32_t packbf2(float lo, float hi) {
    __nv_bfloat162 t = __floats2bfloat162_rn(lo, hi);
    return *(uint32_t*)&t;
}

// ---------------- pre-processing kernels ------------------------------------
__global__ void split_x_kernel(const float* __restrict__ X) {
    int i = blockIdx.x * blockDim.x + threadIdx.x;
    if (i < S_LEN * HID) {
        float x = X[i];
        __nv_bfloat16 h = __float2bfloat16(x);
        g_Xhi[i] = h;
        g_Xlo[i] = __float2bfloat16(x - __bfloat162float(h));
    }
}

__global__ void transpose_split(const float* __restrict__ W, int K, int N,
                                int dstSel, size_t dstOff) {
    __nv_bfloat16* Th = (dstSel ? g_Wo_hi : g_Wt_hi) + dstOff;
    __nv_bfloat16* Tl = (dstSel ? g_Wo_lo : g_Wt_lo) + dstOff;
    __shared__ float t[32][33];
    int n0 = blockIdx.x * 32, k0 = blockIdx.y * 32;
    int tx = threadIdx.x, ty = threadIdx.y;
#pragma unroll
    for (int i = 0; i < 32; i += 8)
        t[ty + i][tx] = W[(size_t)(k0 + ty + i) * N + n0 + tx];
    __syncthreads();
#pragma unroll
    for (int i = 0; i < 32; i += 8) {
        int n = n0 + ty + i, k = k0 + tx;
        float x = t[tx][ty + i];
        __nv_bfloat16 h = __float2bfloat16(x);
        Th[(size_t)n * K + k] = h;
        Tl[(size_t)n * K + k] = __float2bfloat16(x - __bfloat162float(h));
    }
}

// ---------------- HMMA bf16x3 GEMM mainloop (CTA 128x128, 2 CTAs/SM) --------
#define BK 32
#define TSTRIDE 40
#define TILE_BYTES (128 * TSTRIDE * 2)   // 10240
#define STAGE_BYTES (4 * TILE_BYTES)     // 40960: Ah | Al | Bh | Bl
#define GEMM_SMEM (2 * STAGE_BYTES)      // 81920

// acc: [2][8][4], warp tile 32x64
__device__ __forceinline__ void gemm_mainloop(
    const __nv_bfloat16* __restrict__ Ah, const __nv_bfloat16* __restrict__ Al,
    const __nv_bfloat16* __restrict__ Bh, const __nv_bfloat16* __restrict__ Bl,
    int Kd, int bm, int bnB, float acc[2][8][4], char* smem)
{
    const uint32_t sbase = smem_u32(smem);
    const int tid  = threadIdx.x;
    const int wid  = tid >> 5;
    const int lane = tid & 31;
    const int nch  = Kd >> 5;

    const int mbase = (wid >> 1) * 32;
    const int nbase = (wid & 1) * 64;

    const int rowA = mbase + (lane & 15);
    const int colA = (lane >> 4) << 3;
    const int rowB = nbase + (lane & 7) + ((lane >> 4) << 3);
    const int colB = ((lane >> 3) & 1) << 3;

#pragma unroll
    for (int mt = 0; mt < 2; ++mt)
#pragma unroll
        for (int nb = 0; nb < 8; ++nb)
#pragma unroll
            for (int q = 0; q < 4; ++q) acc[mt][nb][q] = 0.f;

    auto load_stage = [&](int ci, int buf) {
        const int k0 = ci << 5;
        const uint32_t st = sbase + buf * STAGE_BYTES;
#pragma unroll
        for (int it = 0; it < 8; ++it) {
            int u = tid + it * 256;
            int mat = u >> 9;            // 0 Ah, 1 Al, 2 Bh, 3 Bl
            int v = u & 511;
            int row = v >> 2;
            int seg = v & 3;
            const __nv_bfloat16* src;
            if (mat == 0)      src = Ah + (size_t)(bm + row) * Kd + k0 + seg * 8;
            else if (mat == 1) src = Al + (size_t)(bm + row) * Kd + k0 + seg * 8;
            else if (mat == 2) src = Bh + (size_t)(bnB + row) * Kd + k0 + seg * 8;
            else               src = Bl + (size_t)(bnB + row) * Kd + k0 + seg * 8;
            cp_async16(st + mat * TILE_BYTES + row * (TSTRIDE * 2) + seg * 16, src);
        }
        CP_COMMIT();
    };

    load_stage(0, 0);

    for (int i = 0; i < nch; ++i) {
        const int b = i & 1;
        CP_WAIT(0);                 // stage i copies done (this thread)
        __syncthreads();            // publish stage i; retire stage i-1
        if (i + 1 < nch) load_stage(i + 1, b ^ 1);   // overlaps with MMAs below

        const uint32_t sb = sbase + b * STAGE_BYTES;
#pragma unroll
        for (int kk = 0; kk < BK; kk += 16) {
            uint32_t fAh[2][4], fAl[2][4], fBh[4][4], fBl[4][4];
#pragma unroll
            for (int mt = 0; mt < 2; ++mt) {
                uint32_t ra = sb + ((rowA + mt * 16) * TSTRIDE + kk + colA) * 2;
                ldm4(fAh[mt], ra);
                ldm4(fAl[mt], ra + TILE_BYTES);
            }
#pragma unroll
            for (int jp = 0; jp < 4; ++jp) {
                uint32_t rb = sb + 2 * TILE_BYTES +
                              ((rowB + jp * 16) * TSTRIDE + kk + colB) * 2;
                ldm4(fBh[jp], rb);
                ldm4(fBl[jp], rb + TILE_BYTES);
            }
#pragma unroll
            for (int mt = 0; mt < 2; ++mt)
#pragma unroll
                for (int nb = 0; nb < 8; ++nb) {
                    const uint32_t* bh = &fBh[nb >> 1][(nb & 1) * 2];
                    const uint32_t* bl = &fBl[nb >> 1][(nb & 1) * 2];
                    mma16816(acc[mt][nb], fAh[mt], bh);
                    mma16816(acc[mt][nb], fAh[mt], bl);
                    mma16816(acc[mt][nb], fAl[mt], bh);
                }
        }
    }
    __syncthreads();   // safe to reuse smem in epilogue
}

// ---- QKV GEMM with fused RoPE + bf16 hi/lo split epilogue -------------------
__global__ __launch_bounds__(256) void qkv_gemm_kernel(const int* __restrict__ pid)
{
    extern __shared__ char smem[];
    const int bn = blockIdx.x * 128;        // column block = one head
    const int bm = blockIdx.y * 128;

    float acc[2][8][4];
    gemm_mainloop(g_Xhi, g_Xlo, g_Wt_hi, g_Wt_lo, HID, bm, bn, acc, smem);

    const int tid  = threadIdx.x;
    const int wid  = tid >> 5;
    const int lane = tid & 31;
    const int mbase = (wid >> 1) * 32;
    const int nbase = (wid & 1) * 64;

    // stage fp32 tile [128][132]
    float* sm = (float*)smem;
#pragma unroll
    for (int mt = 0; mt < 2; ++mt)
#pragma unroll
        for (int nb = 0; nb < 8; ++nb) {
            int r0 = mbase + mt * 16 + (lane >> 2);
            int c0 = nbase + nb * 8 + (lane & 3) * 2;
            *(float2*)&sm[r0 * 132 + c0]       = make_float2(acc[mt][nb][0], acc[mt][nb][1]);
            *(float2*)&sm[(r0 + 8) * 132 + c0] = make_float2(acc[mt][nb][2], acc[mt][nb][3]);
        }
    __syncthreads();

    // rope (Q/K) + hi/lo split, write packed 4x bf16
    const bool isV = (bn >= HID + 512);
    __nv_bfloat16 *Dh, *Dl;
    int ldd, cbase;
    if (bn < HID)            { Dh = g_Qh; Dl = g_Ql; ldd = HID;    cbase = bn; }
    else if (bn < HID + 512) { Dh = g_Kh; Dl = g_Kl; ldd = KV_DIM; cbase = bn - HID; }
    else                     { Dh = g_Vh; Dl = g_Vl; ldd = KV_DIM; cbase = bn - HID - 512; }

#pragma unroll
    for (int k = 0; k < 8; ++k) {
        int u = tid + k * 256;          // 0..2047
        int row = u >> 4;
        int i0 = (u & 15) * 4;
        float y0[4], y1[4];
        if (!isV) {
            float pos = (float)pid[bm + row];
#pragma unroll
            for (int j = 0; j < 4; ++j) {
                int i = i0 + j;
                float x0 = sm[row * 132 + i];
                float x1 = sm[row * 132 + i + 64];
                float inv_freq = expf(-(float)i * 0.21586735246819178f);
                float sv, cv;
                sincosf(pos * inv_freq, &sv, &cv);
                y0[j] = x0 * cv - x1 * sv;
                y1[j] = x1 * cv + x0 * sv;
            }
        } else {
#pragma unroll
            for (int j = 0; j < 4; ++j) {
                y0[j] = sm[row * 132 + i0 + j];
                y1[j] = sm[row * 132 + i0 + j + 64];
            }
        }
        size_t d0 = (size_t)(bm + row) * ldd + cbase + i0;
        size_t d1 = d0 + 64;
        __nv_bfloat16 h[8]; float r[8];
#pragma unroll
        for (int j = 0; j < 4; ++j) {
            h[j]     = __float2bfloat16(y0[j]);
            r[j]     = y0[j] - __bfloat162float(h[j]);
            h[j + 4] = __float2bfloat16(y1[j]);
            r[j + 4] = y1[j] - __bfloat162float(h[j + 4]);
        }
        *(__nv_bfloat162*)&Dh[d0]     = __halves2bfloat162(h[0], h[1]);
        *(__nv_bfloat162*)&Dh[d0 + 2] = __halves2bfloat162(h[2], h[3]);
        *(__nv_bfloat162*)&Dh[d1]     = __halves2bfloat162(h[4], h[5]);
        *(__nv_bfloat162*)&Dh[d1 + 2] = __halves2bfloat162(h[6], h[7]);
        *(__nv_bfloat162*)&Dl[d0]     = __floats2bfloat162_rn(r[0], r[1]);
        *(__nv_bfloat162*)&Dl[d0 + 2] = __floats2bfloat162_rn(r[2], r[3]);
        *(__nv_bfloat162*)&Dl[d1]     = __floats2bfloat162_rn(r[4], r[5]);
        *(__nv_bfloat162*)&Dl[d1 + 2] = __floats2bfloat162_rn(r[6], r[7]);
    }
}

// ---- output projection GEMM (direct fp32 store epilogue) --------------------
__global__ __launch_bounds__(256) void out_gemm_kernel(float* __restrict__ out)
{
    extern __shared__ char smem[];
    const int bn = blockIdx.x * 128;
    const int bm = blockIdx.y * 128;

    float acc[2][8][4];
    gemm_mainloop(g_Ahi, g_Alo, g_Wo_hi, g_Wo_lo, HID, bm, bn, acc, smem);

    const int tid  = threadIdx.x;
    const int wid  = tid >> 5;
    const int lane = tid & 31;
    const int mbase = (wid >> 1) * 32;
    const int nbase = (wid & 1) * 64;

#pragma unroll
    for (int mt = 0; mt < 2; ++mt)
#pragma unroll
        for (int nb = 0; nb < 8; ++nb) {
            int r0 = bm + mbase + mt * 16 + (lane >> 2);
            int c0 = bn + nbase + nb * 8 + (lane & 3) * 2;
            float2 v0 = {acc[mt][nb][0], acc[mt][nb][1]};
            float2 v1 = {acc[mt][nb][2], acc[mt][nb][3]};
            *(float2*)(out + (size_t)r0 * HID + c0)       = v0;
            *(float2*)(out + (size_t)(r0 + 8) * HID + c0) = v1;
        }
}

// ---------------- HMMA bf16x3 flash attention --------------------------------
#define FS 136
#define F_QH 0
#define F_QL (64 * FS)
#define F_KH (2 * 64 * FS)
#define F_KL (3 * 64 * FS)
#define F_VH (4 * 64 * FS)
#define F_VL (5 * 64 * FS)
#define FLASH_SMEM (6 * 64 * FS * 2)

__global__ __launch_bounds__(128) void flash_kernel()
{
    const int qt  = (int)gridDim.x - 1 - (int)blockIdx.x;
    const int h   = blockIdx.y;
    const int kvh = h / (NH / NKV);

    extern __shared__ __nv_bfloat16 fsm[];
    const uint32_t sb = smem_u32(fsm);

    const int tid  = threadIdx.x;
    const int w    = tid >> 5;
    const int lane = tid & 31;

    const int rowA   = w * 16 + (lane & 15);
    const int colA   = (lane >> 4) << 3;
    const int rowBo  = (lane & 7) + ((lane >> 4) << 3);
    const int colB   = ((lane >> 3) & 1) << 3;
    const int rowVt  = (lane & 7) + (((lane >> 3) & 1) << 3);
    const int colVt  = (lane >> 4) << 3;

    for (int f = tid; f < 1024; f += 128) {
        int r = f >> 4, seg = f & 15;
        size_t g = (size_t)(qt * 64 + r) * HID + h * 128 + seg * 8;
        *(uint4*)&fsm[F_QH + r * FS + seg * 8] = *(const uint4*)&g_Qh[g];
        *(uint4*)&fsm[F_QL + r * FS + seg * 8] = *(const uint4*)&g_Ql[g];
    }

    float o[16][4];
#pragma unroll
    for (int nb = 0; nb < 16; ++nb)
#pragma unroll
        for (int q = 0; q < 4; ++q) o[nb][q] = 0.f;
    float m0 = -1e30f, m1 = -1e30f, l0 = 0.f, l1 = 0.f;

    const float SL = 0.08838834764831845f * 1.4426950408889634f;

    for (int kt = 0; kt <= qt; ++kt) {
        __syncthreads();
        for (int f = tid; f < 1024; f += 128) {
            int r = f >> 4, seg = f & 15;
            size_t g = (size_t)(kt * 64 + r) * KV_DIM + kvh * 128 + seg * 8;
            *(uint4*)&fsm[F_KH + r * FS + seg * 8] = *(const uint4*)&g_Kh[g];
            *(uint4*)&fsm[F_KL + r * FS + seg * 8] = *(const uint4*)&g_Kl[g];
            *(uint4*)&fsm[F_VH + r * FS + seg * 8] = *(const uint4*)&g_Vh[g];
            *(uint4*)&fsm[F_VL + r * FS + seg * 8] = *(const uint4*)&g_Vl[g];
        }
        __syncthreads();

        float s[8][4];
#pragma unroll
        for (int nb = 0; nb < 8; ++nb)
#pragma unroll
            for (int q = 0; q < 4; ++q) s[nb][q] = 0.f;

#pragma unroll
        for (int ks = 0; ks < 8; ++ks) {
            uint32_t qh[4], ql[4];
            uint32_t ra = sb + (rowA * FS + ks * 16 + colA) * 2;
            ldm4(qh, ra + F_QH * 2);
            ldm4(ql, ra + F_QL * 2);
#pragma unroll
            for (int np = 0; np < 4; ++np) {
                uint32_t kh[4], kl[4];
                uint32_t rb = sb + ((np * 16 + rowBo) * FS + ks * 16 + colB) * 2;
                ldm4(kh, rb + F_KH * 2);
                ldm4(kl, rb + F_KL * 2);
#pragma unroll
                for (int half = 0; half < 2; ++half) {
                    int nb = np * 2 + half;
                    mma16816(s[nb], qh, &kh[half * 2]);
                    mma16816(s[nb], qh, &kl[half * 2]);
                    mma16816(s[nb], ql, &kh[half * 2]);
                }
            }
        }

        const bool diag = (kt == qt);
        const int rl0 = w * 16 + (lane >> 2);
        const int rl1 = rl0 + 8;
        float mx0 = -1e30f, mx1 = -1e30f;
#pragma unroll
        for (int nb = 0; nb < 8; ++nb) {
            int c0 = nb * 8 + (lane & 3) * 2;
#pragma unroll
            for (int q = 0; q < 4; ++q) {
                float v = s[nb][q] * SL;
                if (diag) {
                    int col = c0 + (q & 1);
                    int row = (q < 2) ? rl0 : rl1;
                    if (col > row) v = -1e30f;
                }
                s[nb][q] = v;
            }
            mx0 = fmaxf(mx0, fmaxf(s[nb][0], s[nb][1]));
            mx1 = fmaxf(mx1, fmaxf(s[nb][2], s[nb][3]));
        }
        mx0 = fmaxf(mx0, __shfl_xor_sync(0xffffffffu, mx0, 1));
        mx0 = fmaxf(mx0, __shfl_xor_sync(0xffffffffu, mx0, 2));
        mx1 = fmaxf(mx1, __shfl_xor_sync(0xffffffffu, mx1, 1));
        mx1 = fmaxf(mx1, __shfl_xor_sync(0xffffffffu, mx1, 2));

        float mn0 = fmaxf(m0, mx0), mn1 = fmaxf(m1, mx1);
        float a0 = exp2f(m0 - mn0), a1 = exp2f(m1 - mn1);
        float ls0 = 0.f, ls1 = 0.f;
#pragma unroll
        for (int nb = 0; nb < 8; ++nb) {
            float p0 = exp2f(s[nb][0] - mn0);
            float p1 = exp2f(s[nb][1] - mn0);
            float p2 = exp2f(s[nb][2] - mn1);
            float p3 = exp2f(s[nb][3] - mn1);
            s[nb][0] = p0; s[nb][1] = p1; s[nb][2] = p2; s[nb][3] = p3;
            ls0 += p0 + p1;
            ls1 += p2 + p3;
        }
        ls0 += __shfl_xor_sync(0xffffffffu, ls0, 1);
        ls0 += __shfl_xor_sync(0xffffffffu, ls0, 2);
        ls1 += __shfl_xor_sync(0xffffffffu, ls1, 1);
        ls1 += __shfl_xor_sync(0xffffffffu, ls1, 2);
        l0 = l0 * a0 + ls0;
        l1 = l1 * a1 + ls1;
        m0 = mn0; m1 = mn1;

#pragma unroll
        for (int nb = 0; nb < 16; ++nb) {
            o[nb][0] *= a0; o[nb][1] *= a0;
            o[nb][2] *= a1; o[nb][3] *= a1;
        }

        uint32_t pah[4][4], pal[4][4];
#pragma unroll
        for (int kb = 0; kb < 4; ++kb) {
#pragma unroll
            for (int part = 0; part < 4; ++part) {
                int nb = 2 * kb + (part >> 1);
                float c0 = s[nb][(part & 1) * 2];
                float c1 = s[nb][(part & 1) * 2 + 1];
                __nv_bfloat162 hi2 = __floats2bfloat162_rn(c0, c1);
                pah[kb][part] = *(uint32_t*)&hi2;
                float r0 = c0 - __bfloat162float(hi2.x);
                float r1 = c1 - __bfloat162float(hi2.y);
                pal[kb][part] = packbf2(r0, r1);
            }
        }

#pragma unroll
        for (int kb = 0; kb < 4; ++kb) {
#pragma unroll
            for (int nv = 0; nv < 8; ++nv) {
                uint32_t vh[4], vl[4];
                uint32_t rv = sb + ((kb * 16 + rowVt) * FS + nv * 16 + colVt) * 2;
                ldm4t(vh, rv + F_VH * 2);
                ldm4t(vl, rv + F_VL * 2);
#pragma unroll
                for (int half = 0; half < 2; ++half) {
                    int nbv = nv * 2 + half;
                    mma16816(o[nbv], pah[kb], &vh[half * 2]);
                    mma16816(o[nbv], pal[kb], &vh[half * 2]);
                    mma16816(o[nbv], pah[kb], &vl[half * 2]);
                }
            }
        }
    }

    // normalize + write bf16 hi/lo directly (fused split)
    const float inv0 = 1.0f / l0, inv1 = 1.0f / l1;
    const int r0 = qt * 64 + w * 16 + (lane >> 2);
    const int r1 = r0 + 8;
#pragma unroll
    for (int nb = 0; nb < 16; ++nb) {
        int c = h * 128 + nb * 8 + (lane & 3) * 2;
        float y0 = o[nb][0] * inv0, y1 = o[nb][1] * inv0;
        float y2 = o[nb][2] * inv1, y3 = o[nb][3] * inv1;
        __nv_bfloat162 h01 = __floats2bfloat162_rn(y0, y1);
        __nv_bfloat162 h23 = __floats2bfloat162_rn(y2, y3);
        *(__nv_bfloat162*)&g_Ahi[(size_t)r0 * HID + c] = h01;
        *(__nv_bfloat162*)&g_Ahi[(size_t)r1 * HID + c] = h23;
        __nv_bfloat162 l01 = __floats2bfloat162_rn(y0 - __bfloat162float(h01.x),
                                                   y1 - __bfloat162float(h01.y));
        __nv_bfloat162 l23 = __floats2bfloat162_rn(y2 - __bfloat162float(h23.x),
                                                   y3 - __bfloat162float(h23.y));
        *(__nv_bfloat162*)&g_Alo[(size_t)r0 * HID + c] = l01;
        *(__nv_bfloat162*)&g_Alo[(size_t)r1 * HID + c] = l23;
    }
}

// ---------------------------------------------------------------------------
extern "C" void kernel_launch(void* const* d_in, const int* in_sizes, int n_in,
                              void* d_out, int out_size)
{
    const float* X   = (const float*)d_in[0];
    const int*   pid = (const int*)  d_in[1];
    const float* Wq  = (const float*)d_in[2];
    const float* Wk  = (const float*)d_in[3];
    const float* Wv  = (const float*)d_in[4];
    const float* Wo  = (const float*)d_in[5];
    float* out = (float*)d_out;

    static int attr_set = 0;
    if (!attr_set) {
        cudaFuncSetAttribute(qkv_gemm_kernel, cudaFuncAttributeMaxDynamicSharedMemorySize, GEMM_SMEM);
        cudaFuncSetAttribute(out_gemm_kernel, cudaFuncAttributeMaxDynamicSharedMemorySize, GEMM_SMEM);
        cudaFuncSetAttribute(flash_kernel, cudaFuncAttributeMaxDynamicSharedMemorySize, FLASH_SMEM);
        attr_set = 1;
    }

    split_x_kernel<<<(S_LEN * HID + 255) / 256, 256>>>(X);

    transpose_split<<<dim3(HID / 32, HID / 32), dim3(32, 8)>>>(Wq, HID, HID, 0, 0);
    transpose_split<<<dim3(KV_DIM / 32, HID / 32), dim3(32, 8)>>>(
        Wk, HID, KV_DIM, 0, (size_t)HID * HID);
    transpose_split<<<dim3(KV_DIM / 32, HID / 32), dim3(32, 8)>>>(
        Wv, HID, KV_DIM, 0, (size_t)(HID + 512) * HID);
    transpose_split<<<dim3(HID / 32, HID / 32), dim3(32, 8)>>>(Wo, HID, HID, 1, 0);

    // QKV GEMM with fused RoPE + hi/lo split epilogue
    qkv_gemm_kernel<<<dim3(QKV_N / 128, S_LEN / 128), 256, GEMM_SMEM>>>(pid);

    // flash attention (writes g_Ahi/g_Alo directly)
    flash_kernel<<<dim3(32, 28), 128, FLASH_SMEM>>>();

    // output projection
    out_gemm_kernel<<<dim3(HID / 128, S_LEN / 128), 256, GEMM_SMEM>>>(out);
}

// round 10
// speedup vs baseline: 1.0961x; 1.0798x over previous
#include <cuda_runtime.h>
#include <cuda_bf16.h>
#include <math.h>
#include <stdint.h>

#define S_LEN 2048
#define HID   3584
#define NH    28
#define NKV   4
#define HD    128
#define KV_DIM 512
#define QKV_N  4608   // 3584 + 512 + 512

// ---------------- scratch (__device__ globals; no allocs allowed) ----------
__device__ __nv_bfloat16 g_Xhi[S_LEN * HID];
__device__ __nv_bfloat16 g_Xlo[S_LEN * HID];
__device__ __nv_bfloat16 g_Ahi[S_LEN * HID];
__device__ __nv_bfloat16 g_Alo[S_LEN * HID];
__device__ __nv_bfloat16 g_Wt_hi[(size_t)QKV_N * HID];
__device__ __nv_bfloat16 g_Wt_lo[(size_t)QKV_N * HID];
__device__ __nv_bfloat16 g_Wo_hi[(size_t)HID * HID];
__device__ __nv_bfloat16 g_Wo_lo[(size_t)HID * HID];

__device__ __nv_bfloat16 g_Qh[S_LEN * HID];
__device__ __nv_bfloat16 g_Ql[S_LEN * HID];
__device__ __nv_bfloat16 g_Kh[S_LEN * KV_DIM];
__device__ __nv_bfloat16 g_Kl[S_LEN * KV_DIM];
__device__ __nv_bfloat16 g_Vh[S_LEN * KV_DIM];
__device__ __nv_bfloat16 g_Vl[S_LEN * KV_DIM];

__device__ float g_rope_cos[S_LEN * 64];
__device__ float g_rope_sin[S_LEN * 64];

// ---------------- PTX helpers (baseline PTX only) ---------------------------
__device__ __forceinline__ uint32_t smem_u32(const void* p) {
    uint32_t a;
    asm("{ .reg .u64 t; cvta.to.shared.u64 t, %1; cvt.u32.u64 %0, t; }" : "=r"(a) : "l"(p));
    return a;
}
__device__ __forceinline__ void cp_async16(uint32_t dst, const void* src) {
    asm volatile("cp.async.cg.shared.global [%0], [%1], 16;" :: "r"(dst), "l"(src));
}
#define CP_COMMIT() asm volatile("cp.async.commit_group;" ::: "memory")
#define CP_WAIT(N)  asm volatile("cp.async.wait_group %0;" :: "n"(N) : "memory")

__device__ __forceinline__ void ldm4(uint32_t* r, uint32_t addr) {
    asm volatile("ldmatrix.sync.aligned.m8n8.x4.shared.b16 {%0,%1,%2,%3}, [%4];"
        : "=r"(r[0]), "=r"(r[1]), "=r"(r[2]), "=r"(r[3]) : "r"(addr));
}
__device__ __forceinline__ void ldm4t(uint32_t* r, uint32_t addr) {
    asm volatile("ldmatrix.sync.aligned.m8n8.x4.trans.shared.b16 {%0,%1,%2,%3}, [%4];"
        : "=r"(r[0]), "=r"(r[1]), "=r"(r[2]), "=r"(r[3]) : "r"(addr));
}
__device__ __forceinline__ void mma16816(float* c, const uint32_t* a, const uint32_t* b) {
    asm volatile("mma.sync.aligned.m16n8k16.row.col.f32.bf16.bf16.f32 "
        "{%0,%1,%2,%3}, {%4,%5,%6,%7}, {%8,%9}, {%0,%1,%2,%3};"
        : "+f"(c[0]), "+f"(c[1]), "+f"(c[2]), "+f"(c[3])
        : "r"(a[0]), "r"(a[1]), "r"(a[2]), "r"(a[3]), "r"(b[0]), "r"(b[1]));
}
__device__ __forceinline__ uint32_t packbf2(float lo, float hi) {
    __nv_bfloat162 t = __floats2bfloat162_rn(lo, hi);
    return *(uint32_t*)&t;
}

// ---------------- pre-processing kernels ------------------------------------
__global__ void split_x_kernel(const float* __restrict__ X) {
    int i = blockIdx.x * blockDim.x + threadIdx.x;
    if (i < S_LEN * HID) {
        float x = X[i];
        __nv_bfloat16 h = __float2bfloat16(x);
        g_Xhi[i] = h;
        g_Xlo[i] = __float2bfloat16(x - __bfloat162float(h));
    }
}

__global__ void rope_table_kernel(const int* __restrict__ pid) {
    int idx = blockIdx.x * blockDim.x + threadIdx.x;
    if (idx < S_LEN * 64) {
        int s = idx >> 6, i = idx & 63;
        float inv_freq = expf(-(float)i * 0.21586735246819178f);
        float sv, cv;
        sincosf((float)pid[s] * inv_freq, &sv, &cv);
        g_rope_cos[idx] = cv;
        g_rope_sin[idx] = sv;
    }
}

__global__ void transpose_split(const float* __restrict__ W, int K, int N,
                                int dstSel, size_t dstOff) {
    __nv_bfloat16* Th = (dstSel ? g_Wo_hi : g_Wt_hi) + dstOff;
    __nv_bfloat16* Tl = (dstSel ? g_Wo_lo : g_Wt_lo) + dstOff;
    __shared__ float t[32][33];
    int n0 = blockIdx.x * 32, k0 = blockIdx.y * 32;
    int tx = threadIdx.x, ty = threadIdx.y;
#pragma unroll
    for (int i = 0; i < 32; i += 8)
        t[ty + i][tx] = W[(size_t)(k0 + ty + i) * N + n0 + tx];
    __syncthreads();
#pragma unroll
    for (int i = 0; i < 32; i += 8) {
        int n = n0 + ty + i, k = k0 + tx;
        float x = t[tx][ty + i];
        __nv_bfloat16 h = __float2bfloat16(x);
        Th[(size_t)n * K + k] = h;
        Tl[(size_t)n * K + k] = __float2bfloat16(x - __bfloat162float(h));
    }
}

// ---------------- HMMA bf16x3 GEMM: CTA 128x128, 4 warps, warp 64x64 --------
#define BK 32
#define TSTRIDE 40
#define TILE_BYTES (128 * TSTRIDE * 2)   // 10240
#define STAGE_BYTES (4 * TILE_BYTES)     // Ah | Al | Bh | Bl
#define GEMM_SMEM (2 * STAGE_BYTES)      // 81920

__device__ __forceinline__ void gemm_mainloop(
    const __nv_bfloat16* __restrict__ Ah, const __nv_bfloat16* __restrict__ Al,
    const __nv_bfloat16* __restrict__ Bh, const __nv_bfloat16* __restrict__ Bl,
    int Kd, int bm, int bnB, float acc[4][8][4], char* smem)
{
    const uint32_t sbase = smem_u32(smem);
    const int tid  = threadIdx.x;
    const int wid  = tid >> 5;          // 0..3
    const int lane = tid & 31;
    const int nch  = Kd >> 5;

    const int mw = (wid >> 1) * 64;     // warp M offset (0 / 64)
    const int nw = (wid & 1) * 64;      // warp N offset (0 / 64)

    const int rowA = mw + (lane & 15);
    const int colA = (lane >> 4) << 3;
    const int rowB = nw + (lane & 7) + ((lane >> 4) << 3);
    const int colB = ((lane >> 3) & 1) << 3;

#pragma unroll
    for (int mt = 0; mt < 4; ++mt)
#pragma unroll
        for (int nb = 0; nb < 8; ++nb)
#pragma unroll
            for (int q = 0; q < 4; ++q) acc[mt][nb][q] = 0.f;

    // stage loader: 2048 x 16B segments, 16 per thread (128 threads)
    auto load_stage = [&](int ci, int buf) {
        const int k0 = ci << 5;
        const uint32_t st = sbase + buf * STAGE_BYTES;
#pragma unroll
        for (int it = 0; it < 16; ++it) {
            int u = tid + it * 128;
            int mat = u >> 9;            // 0 Ah, 1 Al, 2 Bh, 3 Bl
            int v = u & 511;
            int row = v >> 2;
            int seg = v & 3;
            const __nv_bfloat16* src;
            if (mat == 0)      src = Ah + (size_t)(bm + row) * Kd + k0 + seg * 8;
            else if (mat == 1) src = Al + (size_t)(bm + row) * Kd + k0 + seg * 8;
            else if (mat == 2) src = Bh + (size_t)(bnB + row) * Kd + k0 + seg * 8;
            else               src = Bl + (size_t)(bnB + row) * Kd + k0 + seg * 8;
            cp_async16(st + mat * TILE_BYTES + row * (TSTRIDE * 2) + seg * 16, src);
        }
        CP_COMMIT();
    };

    load_stage(0, 0);

    for (int i = 0; i < nch; ++i) {
        const int b = i & 1;
        if (i + 1 < nch) {
            load_stage(i + 1, b ^ 1);   // issue next, then wait for current
            CP_WAIT(1);
        } else {
            CP_WAIT(0);
        }
        __syncthreads();

        const uint32_t sb = sbase + b * STAGE_BYTES;
#pragma unroll
        for (int kk = 0; kk < BK; kk += 16) {
            uint32_t fAh[4][4], fAl[4][4];
#pragma unroll
            for (int mt = 0; mt < 4; ++mt) {
                uint32_t ra = sb + ((rowA + mt * 16) * TSTRIDE + kk + colA) * 2;
                ldm4(fAh[mt], ra);
                ldm4(fAl[mt], ra + TILE_BYTES);
            }
#pragma unroll
            for (int np = 0; np < 4; ++np) {
                uint32_t fBh[4], fBl[4];
                uint32_t rb = sb + 2 * TILE_BYTES +
                              ((rowB + np * 16) * TSTRIDE + kk + colB) * 2;
                ldm4(fBh, rb);
                ldm4(fBl, rb + TILE_BYTES);
#pragma unroll
                for (int half = 0; half < 2; ++half) {
                    int nb = np * 2 + half;
#pragma unroll
                    for (int mt = 0; mt < 4; ++mt) {
                        mma16816(acc[mt][nb], fAh[mt], &fBh[half * 2]);
                        mma16816(acc[mt][nb], fAh[mt], &fBl[half * 2]);
                        mma16816(acc[mt][nb], fAl[mt], &fBh[half * 2]);
                    }
                }
            }
        }
        __syncthreads();
    }
}

// ---- QKV GEMM with fused RoPE (table) + bf16 hi/lo split epilogue ----------
__global__ __launch_bounds__(128) void qkv_gemm_kernel()
{
    extern __shared__ char smem[];
    const int bn = blockIdx.x * 128;        // column block = one head
    const int bm = blockIdx.y * 128;

    float acc[4][8][4];
    gemm_mainloop(g_Xhi, g_Xlo, g_Wt_hi, g_Wt_lo, HID, bm, bn, acc, smem);

    const int tid  = threadIdx.x;
    const int wid  = tid >> 5;
    const int lane = tid & 31;
    const int mw = (wid >> 1) * 64;
    const int nw = (wid & 1) * 64;

    // stage fp32 tile [128][132]
    float* sm = (float*)smem;
#pragma unroll
    for (int mt = 0; mt < 4; ++mt)
#pragma unroll
        for (int nb = 0; nb < 8; ++nb) {
            int r0 = mw + mt * 16 + (lane >> 2);
            int c0 = nw + nb * 8 + (lane & 3) * 2;
            *(float2*)&sm[r0 * 132 + c0]       = make_float2(acc[mt][nb][0], acc[mt][nb][1]);
            *(float2*)&sm[(r0 + 8) * 132 + c0] = make_float2(acc[mt][nb][2], acc[mt][nb][3]);
        }
    __syncthreads();

    const bool isV = (bn >= HID + 512);
    __nv_bfloat16 *Dh, *Dl;
    int ldd, cbase;
    if (bn < HID)            { Dh = g_Qh; Dl = g_Ql; ldd = HID;    cbase = bn; }
    else if (bn < HID + 512) { Dh = g_Kh; Dl = g_Kl; ldd = KV_DIM; cbase = bn - HID; }
    else                     { Dh = g_Vh; Dl = g_Vl; ldd = KV_DIM; cbase = bn - HID - 512; }

#pragma unroll
    for (int k = 0; k < 16; ++k) {
        int u = tid + k * 128;          // 0..2047
        int row = u >> 4;
        int i0 = (u & 15) * 4;
        float y0[4], y1[4];
        if (!isV) {
            float4 cv = *(const float4*)&g_rope_cos[(size_t)(bm + row) * 64 + i0];
            float4 sv = *(const float4*)&g_rope_sin[(size_t)(bm + row) * 64 + i0];
            float c[4] = {cv.x, cv.y, cv.z, cv.w};
            float s[4] = {sv.x, sv.y, sv.z, sv.w};
#pragma unroll
            for (int j = 0; j < 4; ++j) {
                float x0 = sm[row * 132 + i0 + j];
                float x1 = sm[row * 132 + i0 + j + 64];
                y0[j] = x0 * c[j] - x1 * s[j];
                y1[j] = x1 * c[j] + x0 * s[j];
            }
        } else {
#pragma unroll
            for (int j = 0; j < 4; ++j) {
                y0[j] = sm[row * 132 + i0 + j];
                y1[j] = sm[row * 132 + i0 + j + 64];
            }
        }
        size_t d0 = (size_t)(bm + row) * ldd + cbase + i0;
        size_t d1 = d0 + 64;
        __nv_bfloat16 h[8]; float r[8];
#pragma unroll
        for (int j = 0; j < 4; ++j) {
            h[j]     = __float2bfloat16(y0[j]);
            r[j]     = y0[j] - __bfloat162float(h[j]);
            h[j + 4] = __float2bfloat16(y1[j]);
            r[j + 4] = y1[j] - __bfloat162float(h[j + 4]);
        }
        *(__nv_bfloat162*)&Dh[d0]     = __halves2bfloat162(h[0], h[1]);
        *(__nv_bfloat162*)&Dh[d0 + 2] = __halves2bfloat162(h[2], h[3]);
        *(__nv_bfloat162*)&Dh[d1]     = __halves2bfloat162(h[4], h[5]);
        *(__nv_bfloat162*)&Dh[d1 + 2] = __halves2bfloat162(h[6], h[7]);
        *(__nv_bfloat162*)&Dl[d0]     = __floats2bfloat162_rn(r[0], r[1]);
        *(__nv_bfloat162*)&Dl[d0 + 2] = __floats2bfloat162_rn(r[2], r[3]);
        *(__nv_bfloat162*)&Dl[d1]     = __floats2bfloat162_rn(r[4], r[5]);
        *(__nv_bfloat162*)&Dl[d1 + 2] = __floats2bfloat162_rn(r[6], r[7]);
    }
}

// ---- output projection GEMM (direct fp32 store epilogue) --------------------
__global__ __launch_bounds__(128) void out_gemm_kernel(float* __restrict__ out)
{
    extern __shared__ char smem[];
    const int bn = blockIdx.x * 128;
    const int bm = blockIdx.y * 128;

    float acc[4][8][4];
    gemm_mainloop(g_Ahi, g_Alo, g_Wo_hi, g_Wo_lo, HID, bm, bn, acc, smem);

    const int tid  = threadIdx.x;
    const int wid  = tid >> 5;
    const int lane = tid & 31;
    const int mw = (wid >> 1) * 64;
    const int nw = (wid & 1) * 64;

#pragma unroll
    for (int mt = 0; mt < 4; ++mt)
#pragma unroll
        for (int nb = 0; nb < 8; ++nb) {
            int r0 = bm + mw + mt * 16 + (lane >> 2);
            int c0 = bn + nw + nb * 8 + (lane & 3) * 2;
            float2 v0 = {acc[mt][nb][0], acc[mt][nb][1]};
            float2 v1 = {acc[mt][nb][2], acc[mt][nb][3]};
            *(float2*)(out + (size_t)r0 * HID + c0)       = v0;
            *(float2*)(out + (size_t)(r0 + 8) * HID + c0) = v1;
        }
}

// ---------------- HMMA bf16x3 flash attention --------------------------------
#define FS 136
#define F_QH 0
#define F_QL (64 * FS)
#define F_KH (2 * 64 * FS)
#define F_KL (3 * 64 * FS)
#define F_VH (4 * 64 * FS)
#define F_VL (5 * 64 * FS)
#define FLASH_SMEM (6 * 64 * FS * 2)

__global__ __launch_bounds__(128) void flash_kernel()
{
    const int qt  = (int)gridDim.x - 1 - (int)blockIdx.x;
    const int h   = blockIdx.y;
    const int kvh = h / (NH / NKV);

    extern __shared__ __nv_bfloat16 fsm[];
    const uint32_t sb = smem_u32(fsm);

    const int tid  = threadIdx.x;
    const int w    = tid >> 5;
    const int lane = tid & 31;

    const int rowA   = w * 16 + (lane & 15);
    const int colA   = (lane >> 4) << 3;
    const int rowBo  = (lane & 7) + ((lane >> 4) << 3);
    const int colB   = ((lane >> 3) & 1) << 3;
    const int rowVt  = (lane & 7) + (((lane >> 3) & 1) << 3);
    const int colVt  = (lane >> 4) << 3;

    for (int f = tid; f < 1024; f += 128) {
        int r = f >> 4, seg = f & 15;
        size_t g = (size_t)(qt * 64 + r) * HID + h * 128 + seg * 8;
        *(uint4*)&fsm[F_QH + r * FS + seg * 8] = *(const uint4*)&g_Qh[g];
        *(uint4*)&fsm[F_QL + r * FS + seg * 8] = *(const uint4*)&g_Ql[g];
    }

    float o[16][4];
#pragma unroll
    for (int nb = 0; nb < 16; ++nb)
#pragma unroll
        for (int q = 0; q < 4; ++q) o[nb][q] = 0.f;
    float m0 = -1e30f, m1 = -1e30f, l0 = 0.f, l1 = 0.f;

    const float SL = 0.08838834764831845f * 1.4426950408889634f;

    for (int kt = 0; kt <= qt; ++kt) {
        __syncthreads();
        for (int f = tid; f < 1024; f += 128) {
            int r = f >> 4, seg = f & 15;
            size_t g = (size_t)(kt * 64 + r) * KV_DIM + kvh * 128 + seg * 8;
            *(uint4*)&fsm[F_KH + r * FS + seg * 8] = *(const uint4*)&g_Kh[g];
            *(uint4*)&fsm[F_KL + r * FS + seg * 8] = *(const uint4*)&g_Kl[g];
            *(uint4*)&fsm[F_VH + r * FS + seg * 8] = *(const uint4*)&g_Vh[g];
            *(uint4*)&fsm[F_VL + r * FS + seg * 8] = *(const uint4*)&g_Vl[g];
        }
        __syncthreads();

        float s[8][4];
#pragma unroll
        for (int nb = 0; nb < 8; ++nb)
#pragma unroll
            for (int q = 0; q < 4; ++q) s[nb][q] = 0.f;

#pragma unroll
        for (int ks = 0; ks < 8; ++ks) {
            uint32_t qh[4], ql[4];
            uint32_t ra = sb + (rowA * FS + ks * 16 + colA) * 2;
            ldm4(qh, ra + F_QH * 2);
            ldm4(ql, ra + F_QL * 2);
#pragma unroll
            for (int np = 0; np < 4; ++np) {
                uint32_t kh[4], kl[4];
                uint32_t rb = sb + ((np * 16 + rowBo) * FS + ks * 16 + colB) * 2;
                ldm4(kh, rb + F_KH * 2);
                ldm4(kl, rb + F_KL * 2);
#pragma unroll
                for (int half = 0; half < 2; ++half) {
                    int nb = np * 2 + half;
                    mma16816(s[nb], qh, &kh[half * 2]);
                    mma16816(s[nb], qh, &kl[half * 2]);
                    mma16816(s[nb], ql, &kh[half * 2]);
                }
            }
        }

        const bool diag = (kt == qt);
        const int rl0 = w * 16 + (lane >> 2);
        const int rl1 = rl0 + 8;
        float mx0 = -1e30f, mx1 = -1e30f;
#pragma unroll
        for (int nb = 0; nb < 8; ++nb) {
            int c0 = nb * 8 + (lane & 3) * 2;
#pragma unroll
            for (int q = 0; q < 4; ++q) {
                float v = s[nb][q] * SL;
                if (diag) {
                    int col = c0 + (q & 1);
                    int row = (q < 2) ? rl0 : rl1;
                    if (col > row) v = -1e30f;
                }
                s[nb][q] = v;
            }
            mx0 = fmaxf(mx0, fmaxf(s[nb][0], s[nb][1]));
            mx1 = fmaxf(mx1, fmaxf(s[nb][2], s[nb][3]));
        }
        mx0 = fmaxf(mx0, __shfl_xor_sync(0xffffffffu, mx0, 1));
        mx0 = fmaxf(mx0, __shfl_xor_sync(0xffffffffu, mx0, 2));
        mx1 = fmaxf(mx1, __shfl_xor_sync(0xffffffffu, mx1, 1));
        mx1 = fmaxf(mx1, __shfl_xor_sync(0xffffffffu, mx1, 2));

        float mn0 = fmaxf(m0, mx0), mn1 = fmaxf(m1, mx1);
        float a0 = exp2f(m0 - mn0), a1 = exp2f(m1 - mn1);
        float ls0 = 0.f, ls1 = 0.f;
#pragma unroll
        for (int nb = 0; nb < 8; ++nb) {
            float p0 = exp2f(s[nb][0] - mn0);
            float p1 = exp2f(s[nb][1] - mn0);
            float p2 = exp2f(s[nb][2] - mn1);
            float p3 = exp2f(s[nb][3] - mn1);
            s[nb][0] = p0; s[nb][1] = p1; s[nb][2] = p2; s[nb][3] = p3;
            ls0 += p0 + p1;
            ls1 += p2 + p3;
        }
        ls0 += __shfl_xor_sync(0xffffffffu, ls0, 1);
        ls0 += __shfl_xor_sync(0xffffffffu, ls0, 2);
        ls1 += __shfl_xor_sync(0xffffffffu, ls1, 1);
        ls1 += __shfl_xor_sync(0xffffffffu, ls1, 2);
        l0 = l0 * a0 + ls0;
        l1 = l1 * a1 + ls1;
        m0 = mn0; m1 = mn1;

#pragma unroll
        for (int nb = 0; nb < 16; ++nb) {
            o[nb][0] *= a0; o[nb][1] *= a0;
            o[nb][2] *= a1; o[nb][3] *= a1;
        }

        uint32_t pah[4][4], pal[4][4];
#pragma unroll
        for (int kb = 0; kb < 4; ++kb) {
#pragma unroll
            for (int part = 0; part < 4; ++part) {
                int nb = 2 * kb + (part >> 1);
                float c0 = s[nb][(part & 1) * 2];
                float c1 = s[nb][(part & 1) * 2 + 1];
                __nv_bfloat162 hi2 = __floats2bfloat162_rn(c0, c1);
                pah[kb][part] = *(uint32_t*)&hi2;
                float r0 = c0 - __bfloat162float(hi2.x);
                float r1 = c1 - __bfloat162float(hi2.y);
                pal[kb][part] = packbf2(r0, r1);
            }
        }

#pragma unroll
        for (int kb = 0; kb < 4; ++kb) {
#pragma unroll
            for (int nv = 0; nv < 8; ++nv) {
                uint32_t vh[4], vl[4];
                uint32_t rv = sb + ((kb * 16 + rowVt) * FS + nv * 16 + colVt) * 2;
                ldm4t(vh, rv + F_VH * 2);
                ldm4t(vl, rv + F_VL * 2);
#pragma unroll
                for (int half = 0; half < 2; ++half) {
                    int nbv = nv * 2 + half;
                    mma16816(o[nbv], pah[kb], &vh[half * 2]);
                    mma16816(o[nbv], pal[kb], &vh[half * 2]);
                    mma16816(o[nbv], pah[kb], &vl[half * 2]);
                }
            }
        }
    }

    const float inv0 = 1.0f / l0, inv1 = 1.0f / l1;
    const int r0 = qt * 64 + w * 16 + (lane >> 2);
    const int r1 = r0 + 8;
#pragma unroll
    for (int nb = 0; nb < 16; ++nb) {
        int c = h * 128 + nb * 8 + (lane & 3) * 2;
        float y0 = o[nb][0] * inv0, y1 = o[nb][1] * inv0;
        float y2 = o[nb][2] * inv1, y3 = o[nb][3] * inv1;
        __nv_bfloat162 h01 = __floats2bfloat162_rn(y0, y1);
        __nv_bfloat162 h23 = __floats2bfloat162_rn(y2, y3);
        *(__nv_bfloat162*)&g_Ahi[(size_t)r0 * HID + c] = h01;
        *(__nv_bfloat162*)&g_Ahi[(size_t)r1 * HID + c] = h23;
        __nv_bfloat162 l01 = __floats2bfloat162_rn(y0 - __bfloat162float(h01.x),
                                                   y1 - __bfloat162float(h01.y));
        __nv_bfloat162 l23 = __floats2bfloat162_rn(y2 - __bfloat162float(h23.x),
                                                   y3 - __bfloat162float(h23.y));
        *(__nv_bfloat162*)&g_Alo[(size_t)r0 * HID + c] = l01;
        *(__nv_bfloat162*)&g_Alo[(size_t)r1 * HID + c] = l23;
    }
}

// ---------------------------------------------------------------------------
extern "C" void kernel_launch(void* const* d_in, const int* in_sizes, int n_in,
                              void* d_out, int out_size)
{
    const float* X   = (const float*)d_in[0];
    const int*   pid = (const int*)  d_in[1];
    const float* Wq  = (const float*)d_in[2];
    const float* Wk  = (const float*)d_in[3];
    const float* Wv  = (const float*)d_in[4];
    const float* Wo  = (const float*)d_in[5];
    float* out = (float*)d_out;

    static int attr_set = 0;
    if (!attr_set) {
        cudaFuncSetAttribute(qkv_gemm_kernel, cudaFuncAttributeMaxDynamicSharedMemorySize, GEMM_SMEM);
        cudaFuncSetAttribute(out_gemm_kernel, cudaFuncAttributeMaxDynamicSharedMemorySize, GEMM_SMEM);
        cudaFuncSetAttribute(flash_kernel, cudaFuncAttributeMaxDynamicSharedMemorySize, FLASH_SMEM);
        attr_set = 1;
    }

    split_x_kernel<<<(S_LEN * HID + 255) / 256, 256>>>(X);
    rope_table_kernel<<<(S_LEN * 64 + 255) / 256, 256>>>(pid);

    transpose_split<<<dim3(HID / 32, HID / 32), dim3(32, 8)>>>(Wq, HID, HID, 0, 0);
    transpose_split<<<dim3(KV_DIM / 32, HID / 32), dim3(32, 8)>>>(
        Wk, HID, KV_DIM, 0, (size_t)HID * HID);
    transpose_split<<<dim3(KV_DIM / 32, HID / 32), dim3(32, 8)>>>(
        Wv, HID, KV_DIM, 0, (size_t)(HID + 512) * HID);
    transpose_split<<<dim3(HID / 32, HID / 32), dim3(32, 8)>>>(Wo, HID, HID, 1, 0);

    // QKV GEMM with fused RoPE(table) + hi/lo split epilogue
    qkv_gemm_kernel<<<dim3(QKV_N / 128, S_LEN / 128), 128, GEMM_SMEM>>>();

    // flash attention (writes g_Ahi/g_Alo directly)
    flash_kernel<<<dim3(32, 28), 128, FLASH_SMEM>>>();

    // output projection
    out_gemm_kernel<<<dim3(HID / 128, S_LEN / 128), 128, GEMM_SMEM>>>(out);
}